// round 2
// baseline (speedup 1.0000x reference)
#include <cuda_runtime.h>
#include <math.h>

#define S_TOT 3328
#define S_TXT 256
#define S_IMG 3072
#define DM    1920
#define NH    30
#define HD    64

// Scratch (device globals: allocation-free per harness rules)
__device__ float g_Q[(size_t)S_TOT * DM];
__device__ float g_K[(size_t)S_TOT * DM];
__device__ float g_V[(size_t)S_TOT * DM];
__device__ float g_O[(size_t)S_TOT * DM];

// ---------------------------------------------------------------------------
// GEMM C = A @ W^T + b.  A = concat(enc, hid) rows. 128x128 tile, BK=8,
// 256 threads, 8x8 microtile. W is [N,K] row-major (so W^T access = W[n][k]).
// ---------------------------------------------------------------------------
__global__ __launch_bounds__(256) void gemm_qkv(
    const float* __restrict__ hid, const float* __restrict__ enc,
    const float* __restrict__ W, const float* __restrict__ bias, int which)
{
    __shared__ float As[8][128];
    __shared__ float Bs[8][128];
    float* __restrict__ C = (which == 0) ? g_Q : (which == 1) ? g_K : g_V;

    const int tid = threadIdx.x;
    const int ty = tid >> 4, tx = tid & 15;
    const int m0 = blockIdx.y * 128;
    const int n0 = blockIdx.x * 128;
    const int lr = tid >> 1;          // row within tile (0..127)
    const int lk = (tid & 1) * 4;     // k offset (0 or 4)

    const float* arow_base;
    {
        int gm = m0 + lr;
        arow_base = (gm < S_TXT) ? (enc + (size_t)gm * DM)
                                 : (hid + (size_t)(gm - S_TXT) * DM);
    }
    const float* brow_base = W + (size_t)(n0 + lr) * DM;

    float acc[8][8];
    #pragma unroll
    for (int i = 0; i < 8; i++)
        #pragma unroll
        for (int j = 0; j < 8; j++) acc[i][j] = 0.f;

    for (int k0 = 0; k0 < DM; k0 += 8) {
        float4 av = *(const float4*)(arow_base + k0 + lk);
        float4 bv = *(const float4*)(brow_base + k0 + lk);
        As[lk+0][lr] = av.x; As[lk+1][lr] = av.y; As[lk+2][lr] = av.z; As[lk+3][lr] = av.w;
        Bs[lk+0][lr] = bv.x; Bs[lk+1][lr] = bv.y; Bs[lk+2][lr] = bv.z; Bs[lk+3][lr] = bv.w;
        __syncthreads();
        #pragma unroll
        for (int k = 0; k < 8; k++) {
            float a[8], b[8];
            *(float4*)(a)     = *(const float4*)&As[k][ty*8];
            *(float4*)(a + 4) = *(const float4*)&As[k][ty*8 + 4];
            *(float4*)(b)     = *(const float4*)&Bs[k][tx*8];
            *(float4*)(b + 4) = *(const float4*)&Bs[k][tx*8 + 4];
            #pragma unroll
            for (int i = 0; i < 8; i++)
                #pragma unroll
                for (int j = 0; j < 8; j++)
                    acc[i][j] = fmaf(a[i], b[j], acc[i][j]);
        }
        __syncthreads();
    }

    #pragma unroll
    for (int i = 0; i < 8; i++) {
        int gm = m0 + ty*8 + i;
        float* dst = C + (size_t)gm * DM + n0 + tx*8;
        #pragma unroll
        for (int j = 0; j < 8; j += 4) {
            int gn = n0 + tx*8 + j;
            float4 o;
            o.x = acc[i][j+0] + bias[gn+0];
            o.y = acc[i][j+1] + bias[gn+1];
            o.z = acc[i][j+2] + bias[gn+2];
            o.w = acc[i][j+3] + bias[gn+3];
            *(float4*)(dst + j) = o;
        }
    }
}

// ---------------------------------------------------------------------------
// Output projection: out = g_O @ Wo^T + bo, split into (img rows, txt rows).
// ---------------------------------------------------------------------------
__global__ __launch_bounds__(256) void gemm_out(
    const float* __restrict__ W, const float* __restrict__ bias,
    float* __restrict__ out)
{
    __shared__ float As[8][128];
    __shared__ float Bs[8][128];

    const int tid = threadIdx.x;
    const int ty = tid >> 4, tx = tid & 15;
    const int m0 = blockIdx.y * 128;
    const int n0 = blockIdx.x * 128;
    const int lr = tid >> 1;
    const int lk = (tid & 1) * 4;

    const float* arow_base = g_O + (size_t)(m0 + lr) * DM;
    const float* brow_base = W + (size_t)(n0 + lr) * DM;

    float acc[8][8];
    #pragma unroll
    for (int i = 0; i < 8; i++)
        #pragma unroll
        for (int j = 0; j < 8; j++) acc[i][j] = 0.f;

    for (int k0 = 0; k0 < DM; k0 += 8) {
        float4 av = *(const float4*)(arow_base + k0 + lk);
        float4 bv = *(const float4*)(brow_base + k0 + lk);
        As[lk+0][lr] = av.x; As[lk+1][lr] = av.y; As[lk+2][lr] = av.z; As[lk+3][lr] = av.w;
        Bs[lk+0][lr] = bv.x; Bs[lk+1][lr] = bv.y; Bs[lk+2][lr] = bv.z; Bs[lk+3][lr] = bv.w;
        __syncthreads();
        #pragma unroll
        for (int k = 0; k < 8; k++) {
            float a[8], b[8];
            *(float4*)(a)     = *(const float4*)&As[k][ty*8];
            *(float4*)(a + 4) = *(const float4*)&As[k][ty*8 + 4];
            *(float4*)(b)     = *(const float4*)&Bs[k][tx*8];
            *(float4*)(b + 4) = *(const float4*)&Bs[k][tx*8 + 4];
            #pragma unroll
            for (int i = 0; i < 8; i++)
                #pragma unroll
                for (int j = 0; j < 8; j++)
                    acc[i][j] = fmaf(a[i], b[j], acc[i][j]);
        }
        __syncthreads();
    }

    #pragma unroll
    for (int i = 0; i < 8; i++) {
        int gm = m0 + ty*8 + i;
        size_t orow = (gm < S_TXT) ? (size_t)(S_IMG + gm) : (size_t)(gm - S_TXT);
        float* dst = out + orow * DM + n0 + tx*8;
        #pragma unroll
        for (int j = 0; j < 8; j += 4) {
            int gn = n0 + tx*8 + j;
            float4 o;
            o.x = acc[i][j+0] + bias[gn+0];
            o.y = acc[i][j+1] + bias[gn+1];
            o.z = acc[i][j+2] + bias[gn+2];
            o.w = acc[i][j+3] + bias[gn+3];
            *(float4*)(dst + j) = o;
        }
    }
}

// ---------------------------------------------------------------------------
// LayerNorm (fp32, per (s,h) over hd=64) + RoPE on image tokens. In place.
// One warp per (s,h); each lane holds d=lane and d=lane+32.
// ---------------------------------------------------------------------------
__global__ __launch_bounds__(256) void ln_rope(
    const float* __restrict__ cosb, const float* __restrict__ sinb, int which)
{
    float* __restrict__ X = which ? g_K : g_Q;
    int w = blockIdx.x * 8 + (threadIdx.x >> 5);
    int lane = threadIdx.x & 31;
    int s = w / NH;
    int h = w - s * NH;
    if (s >= S_TOT) return;

    float* p = X + (size_t)s * DM + h * HD;
    float x0 = p[lane], x1 = p[lane + 32];

    float sum = x0 + x1;
    #pragma unroll
    for (int o = 16; o; o >>= 1) sum += __shfl_xor_sync(0xffffffffu, sum, o);
    float mu = sum * (1.0f / 64.0f);

    float d0 = x0 - mu, d1 = x1 - mu;
    float vs = fmaf(d0, d0, d1 * d1);
    #pragma unroll
    for (int o = 16; o; o >>= 1) vs += __shfl_xor_sync(0xffffffffu, vs, o);
    float inv = rsqrtf(fmaf(vs, 1.0f / 64.0f, 1e-5f));

    float y0 = d0 * inv, y1 = d1 * inv;

    if (s >= S_TXT) {
        int sp = s - S_TXT;
        const float* cr = cosb + (size_t)sp * HD;
        const float* sr = sinb + (size_t)sp * HD;
        float c0 = cr[lane], c1 = cr[lane + 32];
        float s0 = sr[lane], s1 = sr[lane + 32];
        // d<32: rot = -x[d+32]; d>=32: rot = x[d-32]
        float o0 = fmaf(y0, c0, -y1 * s0);
        float o1 = fmaf(y1, c1,  y0 * s1);
        y0 = o0; y1 = o1;
    }
    p[lane] = y0;
    p[lane + 32] = y1;
}

// ---------------------------------------------------------------------------
// Flash attention: CTA = (64-query block, head). Online softmax, K/V streamed
// in 64-key tiles. Qs/KP staged d-major ([d][row]) for conflict-free float4
// LDS; P written transposed into the K buffer for the PV phase.
// ---------------------------------------------------------------------------
__global__ __launch_bounds__(256) void attn_kernel()
{
    __shared__ float Qs[64][64];  // [d][qrow]
    __shared__ float KP[64][64];  // K as [d][key], then P as [key][qrow]
    __shared__ float Vs[64][64];  // [key][d]

    const int h  = blockIdx.y;
    const int m0 = blockIdx.x * 64;
    const int tid = threadIdx.x;
    const int ty = tid >> 4, tx = tid & 15;

    // Load Q tile (transposed into [d][row])
    #pragma unroll
    for (int it = 0; it < 4; it++) {
        int f = tid + it * 256;          // float4 index 0..1023
        int row = f >> 4;
        int d4  = (f & 15) * 4;
        float4 v = *(const float4*)(g_Q + (size_t)(m0 + row) * DM + h * HD + d4);
        Qs[d4+0][row] = v.x; Qs[d4+1][row] = v.y; Qs[d4+2][row] = v.z; Qs[d4+3][row] = v.w;
    }

    float m[4], l[4], acc[4][4];
    #pragma unroll
    for (int i = 0; i < 4; i++) {
        m[i] = -3.4e38f; l[i] = 0.f;
        #pragma unroll
        for (int j = 0; j < 4; j++) acc[i][j] = 0.f;
    }

    for (int n0 = 0; n0 < S_TOT; n0 += 64) {
        __syncthreads();   // previous tile fully consumed
        #pragma unroll
        for (int it = 0; it < 4; it++) {
            int f = tid + it * 256;
            int row = f >> 4;
            int d4  = (f & 15) * 4;
            size_t gidx = (size_t)(n0 + row) * DM + h * HD + d4;
            float4 kv = *(const float4*)(g_K + gidx);
            KP[d4+0][row] = kv.x; KP[d4+1][row] = kv.y; KP[d4+2][row] = kv.z; KP[d4+3][row] = kv.w;
            float4 vv = *(const float4*)(g_V + gidx);
            *(float4*)&Vs[row][d4] = vv;
        }
        __syncthreads();

        // S = Q @ K^T  (rows ty*4.., key-cols tx*4..)
        float s_[4][4];
        #pragma unroll
        for (int i = 0; i < 4; i++)
            #pragma unroll
            for (int j = 0; j < 4; j++) s_[i][j] = 0.f;

        #pragma unroll 16
        for (int d = 0; d < 64; d++) {
            float4 q  = *(const float4*)&Qs[d][ty*4];
            float4 kk = *(const float4*)&KP[d][tx*4];
            float qa[4] = {q.x, q.y, q.z, q.w};
            float ka[4] = {kk.x, kk.y, kk.z, kk.w};
            #pragma unroll
            for (int i = 0; i < 4; i++)
                #pragma unroll
                for (int j = 0; j < 4; j++)
                    s_[i][j] = fmaf(qa[i], ka[j], s_[i][j]);
        }

        const float sc = 0.125f;   // 1/sqrt(64)
        #pragma unroll
        for (int i = 0; i < 4; i++) {
            #pragma unroll
            for (int j = 0; j < 4; j++) s_[i][j] *= sc;

            float rmax = fmaxf(fmaxf(s_[i][0], s_[i][1]), fmaxf(s_[i][2], s_[i][3]));
            #pragma unroll
            for (int o = 1; o < 16; o <<= 1)
                rmax = fmaxf(rmax, __shfl_xor_sync(0xffffffffu, rmax, o));

            float mn = fmaxf(m[i], rmax);
            float corr = __expf(m[i] - mn);
            float rsum = 0.f;
            #pragma unroll
            for (int j = 0; j < 4; j++) {
                s_[i][j] = __expf(s_[i][j] - mn);
                rsum += s_[i][j];
            }
            #pragma unroll
            for (int o = 1; o < 16; o <<= 1)
                rsum += __shfl_xor_sync(0xffffffffu, rsum, o);

            l[i] = l[i] * corr + rsum;
            m[i] = mn;
            #pragma unroll
            for (int j = 0; j < 4; j++) acc[i][j] *= corr;
        }

        __syncthreads();  // everyone done reading KP as K
        // store P transposed: KP[key][qrow]
        #pragma unroll
        for (int i = 0; i < 4; i++)
            #pragma unroll
            for (int j = 0; j < 4; j++)
                KP[tx*4 + j][ty*4 + i] = s_[i][j];
        __syncthreads();

        // acc += P @ V  (d-cols tx*4..)
        #pragma unroll 16
        for (int kk2 = 0; kk2 < 64; kk2++) {
            float4 p4 = *(const float4*)&KP[kk2][ty*4];
            float4 v4 = *(const float4*)&Vs[kk2][tx*4];
            float pa[4] = {p4.x, p4.y, p4.z, p4.w};
            float va[4] = {v4.x, v4.y, v4.z, v4.w};
            #pragma unroll
            for (int i = 0; i < 4; i++)
                #pragma unroll
                for (int j = 0; j < 4; j++)
                    acc[i][j] = fmaf(pa[i], va[j], acc[i][j]);
        }
    }

    #pragma unroll
    for (int i = 0; i < 4; i++) {
        int gm = m0 + ty*4 + i;
        float inv = 1.0f / l[i];
        float4 o;
        o.x = acc[i][0] * inv; o.y = acc[i][1] * inv;
        o.z = acc[i][2] * inv; o.w = acc[i][3] * inv;
        *(float4*)(g_O + (size_t)gm * DM + h * HD + tx*4) = o;
    }
}

// ---------------------------------------------------------------------------
extern "C" void kernel_launch(void* const* d_in, const int* in_sizes, int n_in,
                              void* d_out, int out_size)
{
    const float* hid = (const float*)d_in[0];   // (1, 3072, 1920)
    const float* enc = (const float*)d_in[1];   // (1, 256, 1920)
    const float* rc  = (const float*)d_in[2];   // (3072, 64)
    const float* rs  = (const float*)d_in[3];   // (3072, 64)
    const float* Wq  = (const float*)d_in[4];
    const float* bq  = (const float*)d_in[5];
    const float* Wk  = (const float*)d_in[6];
    const float* bk  = (const float*)d_in[7];
    const float* Wv  = (const float*)d_in[8];
    const float* bv  = (const float*)d_in[9];
    const float* Wo  = (const float*)d_in[10];
    const float* bo  = (const float*)d_in[11];
    float* out = (float*)d_out;                 // img (3072*1920) then txt (256*1920)

    dim3 gGemm(DM / 128, S_TOT / 128);          // (15, 26)

    gemm_qkv<<<gGemm, 256>>>(hid, enc, Wq, bq, 0);
    gemm_qkv<<<gGemm, 256>>>(hid, enc, Wk, bk, 1);
    gemm_qkv<<<gGemm, 256>>>(hid, enc, Wv, bv, 2);

    int nblk = (S_TOT * NH) / 8;                // 12480 blocks, 8 warps each
    ln_rope<<<nblk, 256>>>(rc, rs, 0);
    ln_rope<<<nblk, 256>>>(rc, rs, 1);

    attn_kernel<<<dim3(S_TOT / 64, NH), 256>>>();

    gemm_out<<<gGemm, 256>>>(Wo, bo, out);
}

// round 4
// speedup vs baseline: 1.5136x; 1.5136x over previous
#include <cuda_runtime.h>
#include <cstdint>
#include <math.h>

#define S_TOT 3328
#define S_TXT 256
#define S_IMG 3072
#define DM    1920
#define NH    30
#define HD    64

// Scratch (device globals: allocation-free per harness rules)
__device__ float g_Q[(size_t)S_TOT * DM];
__device__ float g_K[(size_t)S_TOT * DM];
__device__ float g_V[(size_t)S_TOT * DM];
__device__ float g_O[(size_t)S_TOT * DM];
__device__ float g_A[(size_t)S_TOT * DM];          // tf32-rounded concat(enc,hid)
__device__ float g_W[4][(size_t)DM * DM];          // tf32-rounded Wq,Wk,Wv,Wo

__device__ __forceinline__ float to_tf32(float x) {
    uint32_t b;
    asm("cvt.rna.tf32.f32 %0, %1;" : "=r"(b) : "f"(x));
    return __uint_as_float(b);
}

// m16n8k8 tf32 HMMA (sm_80+; valid on sm_103 base target)
__device__ __forceinline__ void mma_tf32(float* d,
    float a0, float a1, float a2, float a3, float b0, float b1)
{
    asm volatile(
        "mma.sync.aligned.m16n8k8.row.col.f32.tf32.tf32.f32 "
        "{%0,%1,%2,%3}, {%4,%5,%6,%7}, {%8,%9}, {%0,%1,%2,%3};"
        : "+f"(d[0]), "+f"(d[1]), "+f"(d[2]), "+f"(d[3])
        : "r"(__float_as_uint(a0)), "r"(__float_as_uint(a1)),
          "r"(__float_as_uint(a2)), "r"(__float_as_uint(a3)),
          "r"(__float_as_uint(b0)), "r"(__float_as_uint(b1)));
}

// ===========================================================================
// tf32 round-to-nearest copy (float4 granular)
// ===========================================================================
__global__ __launch_bounds__(256) void tf32_round(
    const float* __restrict__ src, float* __restrict__ dst, int n4)
{
    int i = blockIdx.x * blockDim.x + threadIdx.x;
    if (i < n4) {
        float4 v = ((const float4*)src)[i];
        v.x = to_tf32(v.x); v.y = to_tf32(v.y);
        v.z = to_tf32(v.z); v.w = to_tf32(v.w);
        ((float4*)dst)[i] = v;
    }
}

// ===========================================================================
// HMMA tf32 GEMM: C[m,n] = sum_k A[m,k]*W[n,k] + bias[n]
// CTA 128x128, BK=16, double-buffered cp.async. 8 warps (4x2), warp tile
// 32x64. SMEM stride 20 floats -> conflict-free fragment LDS.
// swap_mode: remap output rows (txt <-> img blocks) for the final projection.
// ===========================================================================
#define SSTRIDE 20

__global__ __launch_bounds__(256) void gemm_mma(
    const float* __restrict__ A, const float* __restrict__ W,
    const float* __restrict__ bias, float* __restrict__ C, int swap_mode)
{
    __shared__ float As[2][128][SSTRIDE];
    __shared__ float Bs[2][128][SSTRIDE];

    const int tid  = threadIdx.x;
    const int lane = tid & 31;
    const int warp = tid >> 5;
    const int wm   = (warp >> 1) * 32;   // warp row offset in tile
    const int wn   = (warp & 1) * 64;    // warp col offset in tile
    const int m0   = blockIdx.y * 128;
    const int n0   = blockIdx.x * 128;

    const int lrow = tid >> 2;           // 0..63: row pair loader
    const int lchk = tid & 3;            // 16B chunk within 64B row segment

    float acc[2][8][4];
    #pragma unroll
    for (int i = 0; i < 2; i++)
        #pragma unroll
        for (int j = 0; j < 8; j++)
            #pragma unroll
            for (int c = 0; c < 4; c++) acc[i][j][c] = 0.f;

    // ---- async tile loader: 128 rows x 16 floats (64B = 4 chunks) each ----
    auto load_stage = [&](int s, int kt) {
        int kg = kt * 16 + lchk * 4;
        #pragma unroll
        for (int h = 0; h < 2; h++) {
            int row = lrow + h * 64;
            const float* ga = A + (size_t)(m0 + row) * DM + kg;
            const float* gb = W + (size_t)(n0 + row) * DM + kg;
            uint32_t sa, sb_;
            asm("{ .reg .u64 t; cvta.to.shared.u64 t, %1; cvt.u32.u64 %0, t; }"
                : "=r"(sa) : "l"(&As[s][row][lchk * 4]));
            asm("{ .reg .u64 t; cvta.to.shared.u64 t, %1; cvt.u32.u64 %0, t; }"
                : "=r"(sb_) : "l"(&Bs[s][row][lchk * 4]));
            asm volatile("cp.async.cg.shared.global [%0], [%1], 16;" :: "r"(sa), "l"(ga) : "memory");
            asm volatile("cp.async.cg.shared.global [%0], [%1], 16;" :: "r"(sb_), "l"(gb) : "memory");
        }
    };

    load_stage(0, 0);
    asm volatile("cp.async.commit_group;" ::: "memory");

    const int NKT = DM / 16;   // 120
    for (int kt = 0; kt < NKT; kt++) {
        int s = kt & 1;
        if (kt + 1 < NKT) {
            load_stage(s ^ 1, kt + 1);
            asm volatile("cp.async.commit_group;" ::: "memory");
            asm volatile("cp.async.wait_group 1;" ::: "memory");
        } else {
            asm volatile("cp.async.wait_group 0;" ::: "memory");
        }
        __syncthreads();

        #pragma unroll
        for (int ks = 0; ks < 16; ks += 8) {
            int cA = ks + (lane & 3);
            float a[2][4];
            #pragma unroll
            for (int i = 0; i < 2; i++) {
                int r = wm + i * 16 + (lane >> 2);
                a[i][0] = As[s][r][cA];
                a[i][1] = As[s][r + 8][cA];
                a[i][2] = As[s][r][cA + 4];
                a[i][3] = As[s][r + 8][cA + 4];
            }
            #pragma unroll
            for (int j = 0; j < 8; j++) {
                int r = wn + j * 8 + (lane >> 2);
                float b0 = Bs[s][r][cA];
                float b1 = Bs[s][r][cA + 4];
                mma_tf32(acc[0][j], a[0][0], a[0][1], a[0][2], a[0][3], b0, b1);
                mma_tf32(acc[1][j], a[1][0], a[1][1], a[1][2], a[1][3], b0, b1);
            }
        }
        __syncthreads();
    }

    // ---- epilogue ----
    #pragma unroll
    for (int i = 0; i < 2; i++) {
        int row_lo = m0 + wm + i * 16 + (lane >> 2);
        #pragma unroll
        for (int half = 0; half < 2; half++) {
            int row = row_lo + half * 8;
            size_t orow = (size_t)row;
            if (swap_mode)
                orow = (row < S_TXT) ? (size_t)(S_IMG + row) : (size_t)(row - S_TXT);
            float* dst = C + orow * DM + n0 + wn;
            #pragma unroll
            for (int j = 0; j < 8; j++) {
                int col = j * 8 + (lane & 3) * 2;
                float2 o;
                o.x = acc[i][j][half * 2 + 0] + __ldg(bias + n0 + wn + col);
                o.y = acc[i][j][half * 2 + 1] + __ldg(bias + n0 + wn + col + 1);
                *(float2*)(dst + col) = o;
            }
        }
    }
}

// ---------------------------------------------------------------------------
// LayerNorm (fp32, per (s,h) over hd=64) + RoPE on image tokens. In place.
// ---------------------------------------------------------------------------
__global__ __launch_bounds__(256) void ln_rope(
    const float* __restrict__ cosb, const float* __restrict__ sinb, int which)
{
    float* __restrict__ X = which ? g_K : g_Q;
    int w = blockIdx.x * 8 + (threadIdx.x >> 5);
    int lane = threadIdx.x & 31;
    int s = w / NH;
    int h = w - s * NH;
    if (s >= S_TOT) return;

    float* p = X + (size_t)s * DM + h * HD;
    float x0 = p[lane], x1 = p[lane + 32];

    float sum = x0 + x1;
    #pragma unroll
    for (int o = 16; o; o >>= 1) sum += __shfl_xor_sync(0xffffffffu, sum, o);
    float mu = sum * (1.0f / 64.0f);

    float d0 = x0 - mu, d1 = x1 - mu;
    float vs = fmaf(d0, d0, d1 * d1);
    #pragma unroll
    for (int o = 16; o; o >>= 1) vs += __shfl_xor_sync(0xffffffffu, vs, o);
    float inv = rsqrtf(fmaf(vs, 1.0f / 64.0f, 1e-5f));

    float y0 = d0 * inv, y1 = d1 * inv;

    if (s >= S_TXT) {
        int sp = s - S_TXT;
        const float* cr = cosb + (size_t)sp * HD;
        const float* sr = sinb + (size_t)sp * HD;
        float c0 = cr[lane], c1 = cr[lane + 32];
        float s0 = sr[lane], s1 = sr[lane + 32];
        float o0 = fmaf(y0, c0, -y1 * s0);
        float o1 = fmaf(y1, c1,  y0 * s1);
        y0 = o0; y1 = o1;
    }
    p[lane] = y0;
    p[lane + 32] = y1;
}

// ---------------------------------------------------------------------------
// Flash attention (fp32 FFMA): CTA = (64-query block, head). Online softmax.
// ---------------------------------------------------------------------------
__global__ __launch_bounds__(256) void attn_kernel()
{
    __shared__ float Qs[64][64];  // [d][qrow]
    __shared__ float KP[64][64];  // K as [d][key], then P as [key][qrow]
    __shared__ float Vs[64][64];  // [key][d]

    const int h  = blockIdx.y;
    const int m0 = blockIdx.x * 64;
    const int tid = threadIdx.x;
    const int ty = tid >> 4, tx = tid & 15;

    #pragma unroll
    for (int it = 0; it < 4; it++) {
        int f = tid + it * 256;
        int row = f >> 4;
        int d4  = (f & 15) * 4;
        float4 v = *(const float4*)(g_Q + (size_t)(m0 + row) * DM + h * HD + d4);
        Qs[d4+0][row] = v.x; Qs[d4+1][row] = v.y; Qs[d4+2][row] = v.z; Qs[d4+3][row] = v.w;
    }

    float m[4], l[4], acc[4][4];
    #pragma unroll
    for (int i = 0; i < 4; i++) {
        m[i] = -3.4e38f; l[i] = 0.f;
        #pragma unroll
        for (int j = 0; j < 4; j++) acc[i][j] = 0.f;
    }

    for (int n0 = 0; n0 < S_TOT; n0 += 64) {
        __syncthreads();
        #pragma unroll
        for (int it = 0; it < 4; it++) {
            int f = tid + it * 256;
            int row = f >> 4;
            int d4  = (f & 15) * 4;
            size_t gidx = (size_t)(n0 + row) * DM + h * HD + d4;
            float4 kv = *(const float4*)(g_K + gidx);
            KP[d4+0][row] = kv.x; KP[d4+1][row] = kv.y; KP[d4+2][row] = kv.z; KP[d4+3][row] = kv.w;
            float4 vv = *(const float4*)(g_V + gidx);
            *(float4*)&Vs[row][d4] = vv;
        }
        __syncthreads();

        float s_[4][4];
        #pragma unroll
        for (int i = 0; i < 4; i++)
            #pragma unroll
            for (int j = 0; j < 4; j++) s_[i][j] = 0.f;

        #pragma unroll 16
        for (int d = 0; d < 64; d++) {
            float4 q  = *(const float4*)&Qs[d][ty*4];
            float4 kk = *(const float4*)&KP[d][tx*4];
            float qa[4] = {q.x, q.y, q.z, q.w};
            float ka[4] = {kk.x, kk.y, kk.z, kk.w};
            #pragma unroll
            for (int i = 0; i < 4; i++)
                #pragma unroll
                for (int j = 0; j < 4; j++)
                    s_[i][j] = fmaf(qa[i], ka[j], s_[i][j]);
        }

        const float sc = 0.125f;
        #pragma unroll
        for (int i = 0; i < 4; i++) {
            #pragma unroll
            for (int j = 0; j < 4; j++) s_[i][j] *= sc;

            float rmax = fmaxf(fmaxf(s_[i][0], s_[i][1]), fmaxf(s_[i][2], s_[i][3]));
            #pragma unroll
            for (int o = 1; o < 16; o <<= 1)
                rmax = fmaxf(rmax, __shfl_xor_sync(0xffffffffu, rmax, o));

            float mn = fmaxf(m[i], rmax);
            float corr = __expf(m[i] - mn);
            float rsum = 0.f;
            #pragma unroll
            for (int j = 0; j < 4; j++) {
                s_[i][j] = __expf(s_[i][j] - mn);
                rsum += s_[i][j];
            }
            #pragma unroll
            for (int o = 1; o < 16; o <<= 1)
                rsum += __shfl_xor_sync(0xffffffffu, rsum, o);

            l[i] = l[i] * corr + rsum;
            m[i] = mn;
            #pragma unroll
            for (int j = 0; j < 4; j++) acc[i][j] *= corr;
        }

        __syncthreads();
        #pragma unroll
        for (int i = 0; i < 4; i++)
            #pragma unroll
            for (int j = 0; j < 4; j++)
                KP[tx*4 + j][ty*4 + i] = s_[i][j];
        __syncthreads();

        #pragma unroll 16
        for (int kk2 = 0; kk2 < 64; kk2++) {
            float4 p4 = *(const float4*)&KP[kk2][ty*4];
            float4 v4 = *(const float4*)&Vs[kk2][tx*4];
            float pa[4] = {p4.x, p4.y, p4.z, p4.w};
            float va[4] = {v4.x, v4.y, v4.z, v4.w};
            #pragma unroll
            for (int i = 0; i < 4; i++)
                #pragma unroll
                for (int j = 0; j < 4; j++)
                    acc[i][j] = fmaf(pa[i], va[j], acc[i][j]);
        }
    }

    #pragma unroll
    for (int i = 0; i < 4; i++) {
        int gm = m0 + ty*4 + i;
        float inv = 1.0f / l[i];
        float4 o;
        o.x = acc[i][0] * inv; o.y = acc[i][1] * inv;
        o.z = acc[i][2] * inv; o.w = acc[i][3] * inv;
        *(float4*)(g_O + (size_t)gm * DM + h * HD + tx*4) = o;
    }
}

// ---------------------------------------------------------------------------
extern "C" void kernel_launch(void* const* d_in, const int* in_sizes, int n_in,
                              void* d_out, int out_size)
{
    const float* hid = (const float*)d_in[0];
    const float* enc = (const float*)d_in[1];
    const float* rc  = (const float*)d_in[2];
    const float* rs  = (const float*)d_in[3];
    const float* Wq  = (const float*)d_in[4];
    const float* bq  = (const float*)d_in[5];
    const float* Wk  = (const float*)d_in[6];
    const float* bk  = (const float*)d_in[7];
    const float* Wv  = (const float*)d_in[8];
    const float* bv  = (const float*)d_in[9];
    const float* Wo  = (const float*)d_in[10];
    const float* bo  = (const float*)d_in[11];
    float* out = (float*)d_out;

    float* pA; cudaGetSymbolAddress((void**)&pA, g_A);
    float* pW; cudaGetSymbolAddress((void**)&pW, g_W);
    float* pQ; cudaGetSymbolAddress((void**)&pQ, g_Q);
    float* pK; cudaGetSymbolAddress((void**)&pK, g_K);
    float* pV; cudaGetSymbolAddress((void**)&pV, g_V);
    float* pO; cudaGetSymbolAddress((void**)&pO, g_O);

    // tf32 round-to-nearest prep (so HMMA truncation is exact / unbiased)
    tf32_round<<<(S_TXT*DM/4 + 255)/256, 256>>>(enc, pA, S_TXT*DM/4);
    tf32_round<<<(S_IMG*DM/4 + 255)/256, 256>>>(hid, pA + (size_t)S_TXT*DM, S_IMG*DM/4);
    tf32_round<<<(DM*DM/4 + 255)/256, 256>>>(Wq, pW + 0*(size_t)DM*DM, DM*DM/4);
    tf32_round<<<(DM*DM/4 + 255)/256, 256>>>(Wk, pW + 1*(size_t)DM*DM, DM*DM/4);
    tf32_round<<<(DM*DM/4 + 255)/256, 256>>>(Wv, pW + 2*(size_t)DM*DM, DM*DM/4);
    tf32_round<<<(DM*DM/4 + 255)/256, 256>>>(Wo, pW + 3*(size_t)DM*DM, DM*DM/4);

    dim3 gGemm(DM / 128, S_TOT / 128);          // (15, 26)
    gemm_mma<<<gGemm, 256>>>(pA, pW + 0*(size_t)DM*DM, bq, pQ, 0);
    gemm_mma<<<gGemm, 256>>>(pA, pW + 1*(size_t)DM*DM, bk, pK, 0);
    gemm_mma<<<gGemm, 256>>>(pA, pW + 2*(size_t)DM*DM, bv, pV, 0);

    int nblk = (S_TOT * NH) / 8;
    ln_rope<<<nblk, 256>>>(rc, rs, 0);
    ln_rope<<<nblk, 256>>>(rc, rs, 1);

    attn_kernel<<<dim3(S_TOT / 64, NH), 256>>>();

    tf32_round<<<(S_TOT*DM/4 + 255)/256, 256>>>(pO, pO, S_TOT*DM/4);
    gemm_mma<<<gGemm, 256>>>(pO, pW + 3*(size_t)DM*DM, bo, out, 1);
}